// round 1
// baseline (speedup 1.0000x reference)
#include <cuda_runtime.h>

#define N_NODES 50000
#define D 512
#define N_EDGES 400000

// ---------------- scratch (device globals: allocation-free) ----------------
__device__ __align__(16) float g_msg[(size_t)N_NODES * D];   // msg_sum -> -mean
__device__ __align__(16) float g_cnt[N_NODES];               // in-degree
__device__ __align__(16) float g_Wc[D * D];                  // W1 + W2
__device__ __align__(16) float g_bc[D];                      // b1 + b2

// ---------------- 1. zero scratch ----------------
__global__ void zero_kernel() {
    size_t tid    = (size_t)blockIdx.x * blockDim.x + threadIdx.x;
    size_t stride = (size_t)gridDim.x * blockDim.x;
    float4 z = make_float4(0.f, 0.f, 0.f, 0.f);
    float4* p = reinterpret_cast<float4*>(g_msg);
    size_t total4 = (size_t)N_NODES * D / 4;
    for (size_t i = tid; i < total4; i += stride) p[i] = z;
    for (size_t i = tid; i < N_NODES; i += stride) g_cnt[i] = 0.f;
}

// ---------------- 2. Wc = W1 + W2, bc = b1 + b2 ----------------
__global__ void prep_kernel(const float* __restrict__ W1, const float* __restrict__ W2,
                            const float* __restrict__ b1, const float* __restrict__ b2) {
    int i = blockIdx.x * blockDim.x + threadIdx.x;
    if (i < D * D) g_Wc[i] = W1[i] + W2[i];
    if (i < D)     g_bc[i] = b1[i] + b2[i];
}

// ---------------- 3. edge scatter: g_msg[dst] += x[src], g_cnt[dst] += 1 ----
// 128 threads per edge, one float4 vector-reduction per thread.
__global__ void scatter_kernel(const float* __restrict__ x,
                               const int* __restrict__ src,
                               const int* __restrict__ dst) {
    int e = blockIdx.x * 2 + (threadIdx.x >> 7);
    if (e >= N_EDGES) return;
    int t = threadIdx.x & 127;
    int s = src[e];
    int d = dst[e];
    float4 v = reinterpret_cast<const float4*>(x + (size_t)s * D)[t];
    float* dp = g_msg + (size_t)d * D + t * 4;
    asm volatile("red.global.add.v4.f32 [%0], {%1, %2, %3, %4};"
                 :: "l"(dp), "f"(v.x), "f"(v.y), "f"(v.z), "f"(v.w)
                 : "memory");
    if (t == 0) atomicAdd(&g_cnt[d], 1.0f);
}

// ---------------- 4. g_msg = -msg_sum / max(cnt,1)  (negated mean) ----------
__global__ void mean_kernel() {
    int row = blockIdx.x;
    float c = g_cnt[row];
    float s = -1.0f / fmaxf(c, 1.0f);
    float4* p = reinterpret_cast<float4*>(g_msg + (size_t)row * D);
    float4 v = p[threadIdx.x];
    v.x *= s; v.y *= s; v.z *= s; v.w *= s;
    p[threadIdx.x] = v;
}

// ---------------- 5. fused GEMM: out = [x | -mean] @ [[Wc],[W2]] + bc -------
// 128x128 tile, K=1024 (first 512 from x*Wc, next 512 from (-mean)*W2),
// 256 threads, 8x8 accum per thread. Epilogue applies bias + degree-0 passthrough.
#define BM 128
#define BN 128
#define BK 16
#define TM 8
#define TN 8
#define PAD 4

__global__ __launch_bounds__(256)
void gemm_kernel(const float* __restrict__ x, const float* __restrict__ W2,
                 float* __restrict__ out) {
    __shared__ float As[BK][BM + PAD];
    __shared__ float Bs[BK][BN + PAD];

    const int block_row = blockIdx.y * BM;
    const int block_col = blockIdx.x * BN;
    const int tid = threadIdx.x;
    const int tx  = tid & 15;   // 0..15 -> 8 cols each
    const int ty  = tid >> 4;   // 0..15 -> 8 rows each

    float acc[TM][TN];
#pragma unroll
    for (int i = 0; i < TM; i++)
#pragma unroll
        for (int j = 0; j < TN; j++) acc[i][j] = 0.f;

    for (int kt = 0; kt < 2 * D; kt += BK) {
        // -- load A tile (BM x BK), transpose into As[k][m]
#pragma unroll
        for (int l = 0; l < 2; l++) {
            int f   = tid + l * 256;        // float4 index 0..511
            int ar  = f >> 2;               // row within tile 0..127
            int ac  = (f & 3) * 4;          // k within tile {0,4,8,12}
            int grow = block_row + ar;
            int gk   = kt + ac;
            float4 v = make_float4(0.f, 0.f, 0.f, 0.f);
            if (grow < N_NODES) {
                const float* base = (gk < D)
                    ? (x     + (size_t)grow * D + gk)
                    : (g_msg + (size_t)grow * D + (gk - D));
                v = *reinterpret_cast<const float4*>(base);
            }
            As[ac + 0][ar] = v.x;
            As[ac + 1][ar] = v.y;
            As[ac + 2][ar] = v.z;
            As[ac + 3][ar] = v.w;
        }
        // -- load B tile (BK x BN)
#pragma unroll
        for (int l = 0; l < 2; l++) {
            int f  = tid + l * 256;
            int br = f >> 5;                // k within tile 0..15
            int bc = (f & 31) * 4;          // col within tile
            int gk = kt + br;
            const float* base = (gk < D)
                ? (g_Wc + (size_t)gk * D + block_col + bc)
                : (W2   + (size_t)(gk - D) * D + block_col + bc);
            *reinterpret_cast<float4*>(&Bs[br][bc]) =
                *reinterpret_cast<const float4*>(base);
        }
        __syncthreads();

#pragma unroll
        for (int k = 0; k < BK; k++) {
            float ra[TM], rb[TN];
            *reinterpret_cast<float4*>(&ra[0]) = *reinterpret_cast<const float4*>(&As[k][ty * TM + 0]);
            *reinterpret_cast<float4*>(&ra[4]) = *reinterpret_cast<const float4*>(&As[k][ty * TM + 4]);
            *reinterpret_cast<float4*>(&rb[0]) = *reinterpret_cast<const float4*>(&Bs[k][tx * TN + 0]);
            *reinterpret_cast<float4*>(&rb[4]) = *reinterpret_cast<const float4*>(&Bs[k][tx * TN + 4]);
#pragma unroll
            for (int i = 0; i < TM; i++)
#pragma unroll
                for (int j = 0; j < TN; j++)
                    acc[i][j] += ra[i] * rb[j];
        }
        __syncthreads();
    }

    // -- epilogue: bias + degree-0 passthrough
#pragma unroll
    for (int i = 0; i < TM; i++) {
        int grow = block_row + ty * TM + i;
        if (grow >= N_NODES) break;
        float c = g_cnt[grow];
        bool has = (c > 0.f);
#pragma unroll
        for (int j = 0; j < TN; j += 4) {
            int gcol = block_col + tx * TN + j;
            float4 r;
            if (has) {
                r.x = acc[i][j + 0] + g_bc[gcol + 0];
                r.y = acc[i][j + 1] + g_bc[gcol + 1];
                r.z = acc[i][j + 2] + g_bc[gcol + 2];
                r.w = acc[i][j + 3] + g_bc[gcol + 3];
            } else {
                r = *reinterpret_cast<const float4*>(x + (size_t)grow * D + gcol);
            }
            *reinterpret_cast<float4*>(out + (size_t)grow * D + gcol) = r;
        }
    }
}

// ---------------- launch ----------------
extern "C" void kernel_launch(void* const* d_in, const int* in_sizes, int n_in,
                              void* d_out, int out_size) {
    const float* x  = (const float*)d_in[0];
    const int*   src = (const int*)d_in[1];
    const int*   dst = (const int*)d_in[2];
    const float* W1 = (const float*)d_in[3];
    const float* b1 = (const float*)d_in[4];
    const float* W2 = (const float*)d_in[5];
    const float* b2 = (const float*)d_in[6];
    float* out = (float*)d_out;

    zero_kernel<<<1024, 256>>>();
    prep_kernel<<<(D * D + 255) / 256, 256>>>(W1, W2, b1, b2);
    scatter_kernel<<<(N_EDGES + 1) / 2, 256>>>(x, src, dst);
    mean_kernel<<<N_NODES, 128>>>();
    dim3 grid(D / BN, (N_NODES + BM - 1) / BM);
    gemm_kernel<<<grid, 256>>>(x, W2, out);
}

// round 3
// speedup vs baseline: 1.7664x; 1.7664x over previous
#include <cuda_runtime.h>
#include <cuda_bf16.h>
#include <cstdint>

#define N_NODES 50000
#define D 512
#define N_EDGES 400000
#define KTOT 1024

// ---------------- scratch (device globals: allocation-free) ----------------
__device__ __align__(16) float g_msg[(size_t)N_NODES * D];        // msg_sum
__device__ __align__(16) float g_cnt[N_NODES];                    // in-degree
__device__ __align__(16) float g_bc[D];                           // b1 + b2
__device__ __align__(16) __nv_bfloat16 g_Ahi[(size_t)N_NODES * KTOT];
__device__ __align__(16) __nv_bfloat16 g_Alo[(size_t)N_NODES * KTOT];
__device__ __align__(16) __nv_bfloat16 g_BtHi[(size_t)D * KTOT]; // Bt[n][k]
__device__ __align__(16) __nv_bfloat16 g_BtLo[(size_t)D * KTOT];

// ---------------- asm helpers ----------------
__device__ __forceinline__ uint32_t smem_u32(const void* p) {
    uint32_t a;
    asm("{ .reg .u64 t; cvta.to.shared.u64 t, %1; cvt.u32.u64 %0, t; }" : "=r"(a) : "l"(p));
    return a;
}
__device__ __forceinline__ void cp_async16(uint32_t dst, const void* src, int sz) {
    asm volatile("cp.async.cg.shared.global [%0], [%1], 16, %2;"
                 :: "r"(dst), "l"(src), "r"(sz) : "memory");
}
#define CP_COMMIT() asm volatile("cp.async.commit_group;" ::: "memory")
#define CP_WAIT2()  asm volatile("cp.async.wait_group 2;" ::: "memory")

__device__ __forceinline__ void ldm_x4(uint32_t* d, uint32_t addr) {
    asm volatile("ldmatrix.sync.aligned.m8n8.x4.shared.b16 {%0,%1,%2,%3}, [%4];"
                 : "=r"(d[0]), "=r"(d[1]), "=r"(d[2]), "=r"(d[3]) : "r"(addr));
}
__device__ __forceinline__ void mma_bf16(float* c, const uint32_t* a, const uint32_t* b) {
    asm volatile("mma.sync.aligned.m16n8k16.row.col.f32.bf16.bf16.f32 "
                 "{%0,%1,%2,%3}, {%4,%5,%6,%7}, {%8,%9}, {%0,%1,%2,%3};"
                 : "+f"(c[0]), "+f"(c[1]), "+f"(c[2]), "+f"(c[3])
                 : "r"(a[0]), "r"(a[1]), "r"(a[2]), "r"(a[3]), "r"(b[0]), "r"(b[1]));
}

// ---------------- 1. zero scratch ----------------
__global__ void zero_kernel() {
    size_t tid    = (size_t)blockIdx.x * blockDim.x + threadIdx.x;
    size_t stride = (size_t)gridDim.x * blockDim.x;
    float4 z = make_float4(0.f, 0.f, 0.f, 0.f);
    float4* p = reinterpret_cast<float4*>(g_msg);
    size_t total4 = (size_t)N_NODES * D / 4;
    for (size_t i = tid; i < total4; i += stride) p[i] = z;
    for (size_t i = tid; i < N_NODES; i += stride) g_cnt[i] = 0.f;
}

// ---------------- 2a. bc = b1 + b2 ----------------
__global__ void bias_kernel(const float* __restrict__ b1, const float* __restrict__ b2) {
    int i = blockIdx.x * blockDim.x + threadIdx.x;
    if (i < D) g_bc[i] = b1[i] + b2[i];
}

// ---------------- 2b. BtHi/BtLo = bf16 hi/lo of transpose([[W1+W2],[W2]]) --
__global__ void bprep_kernel(const float* __restrict__ W1, const float* __restrict__ W2) {
    __shared__ float tile[32][33];
    int k0 = blockIdx.x * 32, n0 = blockIdx.y * 32;
    int kk = k0 + threadIdx.y, nn = n0 + threadIdx.x;
    float v = (kk < D) ? (W1[kk * D + nn] + W2[kk * D + nn]) : W2[(kk - D) * D + nn];
    tile[threadIdx.y][threadIdx.x] = v;
    __syncthreads();
    int wn = n0 + threadIdx.y, wk = k0 + threadIdx.x;
    float v2 = tile[threadIdx.x][threadIdx.y];
    __nv_bfloat16 h = __float2bfloat16(v2);
    __nv_bfloat16 l = __float2bfloat16(v2 - __bfloat162float(h));
    g_BtHi[(size_t)wn * KTOT + wk] = h;
    g_BtLo[(size_t)wn * KTOT + wk] = l;
}

// ---------------- 3. edge scatter ----------------
__global__ void scatter_kernel(const float* __restrict__ x,
                               const int* __restrict__ src,
                               const int* __restrict__ dst) {
    int e = blockIdx.x * 2 + (threadIdx.x >> 7);
    if (e >= N_EDGES) return;
    int t = threadIdx.x & 127;
    int s = src[e];
    int d = dst[e];
    float4 v = reinterpret_cast<const float4*>(x + (size_t)s * D)[t];
    float* dp = g_msg + (size_t)d * D + t * 4;
    asm volatile("red.global.add.v4.f32 [%0], {%1, %2, %3, %4};"
                 :: "l"(dp), "f"(v.x), "f"(v.y), "f"(v.z), "f"(v.w)
                 : "memory");
    if (t == 0) atomicAdd(&g_cnt[d], 1.0f);
}

// ---------------- 4. convert: A = [x | -mean] -> bf16 hi/lo ----------------
__global__ void convert_kernel(const float* __restrict__ x) {
    int row = blockIdx.x;
    int t = threadIdx.x;             // 0..127
    int k = t * 8;
    float v[8];
    if (k < D) {
        float4 a = *reinterpret_cast<const float4*>(x + (size_t)row * D + k);
        float4 b = *reinterpret_cast<const float4*>(x + (size_t)row * D + k + 4);
        v[0]=a.x; v[1]=a.y; v[2]=a.z; v[3]=a.w; v[4]=b.x; v[5]=b.y; v[6]=b.z; v[7]=b.w;
    } else {
        float s = -1.0f / fmaxf(g_cnt[row], 1.0f);
        float4 a = *reinterpret_cast<const float4*>(g_msg + (size_t)row * D + (k - D));
        float4 b = *reinterpret_cast<const float4*>(g_msg + (size_t)row * D + (k - D) + 4);
        v[0]=a.x*s; v[1]=a.y*s; v[2]=a.z*s; v[3]=a.w*s; v[4]=b.x*s; v[5]=b.y*s; v[6]=b.z*s; v[7]=b.w*s;
    }
    uint32_t hw[4], lw[4];
#pragma unroll
    for (int i = 0; i < 4; i++) {
        __nv_bfloat16 h0 = __float2bfloat16(v[2*i]);
        __nv_bfloat16 h1 = __float2bfloat16(v[2*i+1]);
        __nv_bfloat16 l0 = __float2bfloat16(v[2*i]   - __bfloat162float(h0));
        __nv_bfloat16 l1 = __float2bfloat16(v[2*i+1] - __bfloat162float(h1));
        hw[i] = (uint32_t)__bfloat16_as_ushort(h0) | ((uint32_t)__bfloat16_as_ushort(h1) << 16);
        lw[i] = (uint32_t)__bfloat16_as_ushort(l0) | ((uint32_t)__bfloat16_as_ushort(l1) << 16);
    }
    *reinterpret_cast<uint4*>(g_Ahi + (size_t)row * KTOT + k) = make_uint4(hw[0], hw[1], hw[2], hw[3]);
    *reinterpret_cast<uint4*>(g_Alo + (size_t)row * KTOT + k) = make_uint4(lw[0], lw[1], lw[2], lw[3]);
}

// ---------------- 5. bf16 mma.sync GEMM with hi/lo compensation ------------
// out = A @ Bt^T + bc ; A = [x | -mean] (M=50000, K=1024), Bt (N=512, K=1024)
// 3 terms: Ahi*Bhi + Ahi*Blo + Alo*Bhi, fp32 accum.
#define BM 128
#define BN 128
#define BKE 32                      // bf16 K elems per chunk
#define ROWB 80                     // smem bytes per tile row (64B data + 16B pad)
#define TILE_B (128 * ROWB)         // 10240 B
#define STAGE_B (4 * TILE_B)        // Ahi, Alo, Bhi, Blo
#define NSTAGE 3
#define NCHUNK (KTOT / BKE)         // 32
#define GEMM_SMEM (NSTAGE * STAGE_B)

__device__ __forceinline__ void load_stage(uint32_t sbase, int tid,
                                           int block_row, int block_col, int kt) {
#pragma unroll
    for (int l = 0; l < 8; l++) {
        int idx  = tid + l * 256;        // 0..2047
        int tile = idx >> 9;             // 0:Ahi 1:Alo 2:Bhi 3:Blo
        int rem  = idx & 511;
        int r    = rem >> 2;             // row 0..127
        int g    = rem & 3;              // 16B granule
        uint32_t dst = sbase + tile * TILE_B + r * ROWB + g * 16;
        const __nv_bfloat16* src;
        int sz = 16;
        if (tile < 2) {
            int grow = block_row + r;
            if (grow >= N_NODES) { grow = N_NODES - 1; sz = 0; }
            src = (tile == 0 ? g_Ahi : g_Alo) + (size_t)grow * KTOT + kt + g * 8;
        } else {
            src = (tile == 2 ? g_BtHi : g_BtLo) + (size_t)(block_col + r) * KTOT + kt + g * 8;
        }
        cp_async16(dst, src, sz);
    }
}

__global__ __launch_bounds__(256, 1)
void gemm_mma_kernel(const float* __restrict__ x, float* __restrict__ out) {
    extern __shared__ char smem[];
    const uint32_t sb0 = smem_u32(smem);
    const int tid  = threadIdx.x;
    const int wid  = tid >> 5;
    const int lane = tid & 31;
    const int block_row = blockIdx.y * BM;
    const int block_col = blockIdx.x * BN;
    const int m0w = (wid & 3) * 32;
    const int n0w = (wid >> 2) * 64;

    float acc[2][8][4];
#pragma unroll
    for (int i = 0; i < 2; i++)
#pragma unroll
        for (int j = 0; j < 8; j++)
#pragma unroll
            for (int q = 0; q < 4; q++) acc[i][j][q] = 0.f;

    // prologue: prefetch 3 stages
#pragma unroll
    for (int s = 0; s < NSTAGE; s++) {
        load_stage(sb0 + s * STAGE_B, tid, block_row, block_col, s * BKE);
        CP_COMMIT();
    }

    const int arow    = lane & 15;
    const int acoloff = (lane >> 4) * 8;
    const int bq      = lane >> 3;
    const int brow    = ((bq >> 1) * 8) + (lane & 7);
    const int bkoff   = (bq & 1) * 8;

    for (int c = 0; c < NCHUNK; c++) {
        CP_WAIT2();
        __syncthreads();
        const uint32_t sb = sb0 + (c % 3) * STAGE_B;

#pragma unroll
        for (int ks = 0; ks < 2; ks++) {
            uint32_t ahi[2][4], alo[2][4], bhi[8][2], blo[8][2];
#pragma unroll
            for (int i = 0; i < 2; i++) {
                uint32_t ad = sb + (m0w + i * 16 + arow) * ROWB + (ks * 16 + acoloff) * 2;
                ldm_x4(ahi[i], ad);
                ldm_x4(alo[i], ad + TILE_B);
            }
#pragma unroll
            for (int jj = 0; jj < 4; jj++) {
                uint32_t bd = sb + 2 * TILE_B + (n0w + jj * 16 + brow) * ROWB + (ks * 16 + bkoff) * 2;
                uint32_t r4[4];
                ldm_x4(r4, bd);
                bhi[jj*2][0] = r4[0]; bhi[jj*2][1] = r4[1];
                bhi[jj*2+1][0] = r4[2]; bhi[jj*2+1][1] = r4[3];
                ldm_x4(r4, bd + TILE_B);
                blo[jj*2][0] = r4[0]; blo[jj*2][1] = r4[1];
                blo[jj*2+1][0] = r4[2]; blo[jj*2+1][1] = r4[3];
            }
#pragma unroll
            for (int i = 0; i < 2; i++)
#pragma unroll
                for (int j = 0; j < 8; j++) {
                    mma_bf16(acc[i][j], ahi[i], bhi[j]);
                    mma_bf16(acc[i][j], ahi[i], blo[j]);
                    mma_bf16(acc[i][j], alo[i], bhi[j]);
                }
        }
        __syncthreads();
        if (c + 3 < NCHUNK)
            load_stage(sb, tid, block_row, block_col, (c + 3) * BKE);
        CP_COMMIT();
    }

    // epilogue: bias + degree-0 passthrough
#pragma unroll
    for (int i = 0; i < 2; i++) {
        int r0 = block_row + m0w + i * 16 + (lane >> 2);
        int r1 = r0 + 8;
        bool v0 = r0 < N_NODES, v1 = r1 < N_NODES;
        float c0 = v0 ? g_cnt[r0] : 0.f;
        float c1 = v1 ? g_cnt[r1] : 0.f;
#pragma unroll
        for (int j = 0; j < 8; j++) {
            int col = block_col + n0w + j * 8 + (lane & 3) * 2;
            float b0 = g_bc[col], b1 = g_bc[col + 1];
            if (v0) {
                float2 o;
                if (c0 > 0.f) { o.x = acc[i][j][0] + b0; o.y = acc[i][j][1] + b1; }
                else { o = *reinterpret_cast<const float2*>(x + (size_t)r0 * D + col); }
                *reinterpret_cast<float2*>(out + (size_t)r0 * D + col) = o;
            }
            if (v1) {
                float2 o;
                if (c1 > 0.f) { o.x = acc[i][j][2] + b0; o.y = acc[i][j][3] + b1; }
                else { o = *reinterpret_cast<const float2*>(x + (size_t)r1 * D + col); }
                *reinterpret_cast<float2*>(out + (size_t)r1 * D + col) = o;
            }
        }
    }
}

// ---------------- launch ----------------
extern "C" void kernel_launch(void* const* d_in, const int* in_sizes, int n_in,
                              void* d_out, int out_size) {
    const float* x   = (const float*)d_in[0];
    const int*   src = (const int*)d_in[1];
    const int*   dst = (const int*)d_in[2];
    const float* W1  = (const float*)d_in[3];
    const float* b1  = (const float*)d_in[4];
    const float* W2  = (const float*)d_in[5];
    const float* b2  = (const float*)d_in[6];
    float* out = (float*)d_out;

    cudaFuncSetAttribute(gemm_mma_kernel, cudaFuncAttributeMaxDynamicSharedMemorySize, GEMM_SMEM);

    zero_kernel<<<1024, 256>>>();
    bias_kernel<<<2, 256>>>(b1, b2);
    {
        dim3 bg(KTOT / 32, D / 32);
        dim3 bb(32, 32);
        bprep_kernel<<<bg, bb>>>(W1, W2);
    }
    scatter_kernel<<<(N_EDGES + 1) / 2, 256>>>(x, src, dst);
    convert_kernel<<<N_NODES, 128>>>(x);
    {
        dim3 grid(D / BN, (N_NODES + BM - 1) / BM);
        gemm_mma_kernel<<<grid, 256, GEMM_SMEM>>>(x, out);
    }
}

// round 4
// speedup vs baseline: 3.0154x; 1.7071x over previous
#include <cuda_runtime.h>
#include <cuda_fp16.h>
#include <cstdint>

#define N_NODES 50000
#define D 512
#define N_EDGES 400000
#define KTOT 1024
#define NSCAN_BLKS 196   // ceil(50000/256)

// ---------------- scratch (device globals: allocation-free) ----------------
__device__ __align__(16) int   g_deg[N_NODES];
__device__ __align__(16) int   g_off[N_NODES];
__device__ __align__(16) int   g_cursor[N_NODES];
__device__ __align__(16) int   g_bsum[256];
__device__ __align__(16) int   g_csr[N_EDGES];                    // src per CSR slot
__device__ __align__(16) float g_bc[D];                           // b1 + b2
__device__ __align__(16) __half g_A[(size_t)N_NODES * KTOT];      // [x | -mean] fp16
__device__ __align__(16) __half g_BtHi[(size_t)D * KTOT];         // Bt[n][k] hi
__device__ __align__(16) __half g_BtLo[(size_t)D * KTOT];         // Bt[n][k] lo

// ---------------- asm helpers ----------------
__device__ __forceinline__ uint32_t smem_u32(const void* p) {
    uint32_t a;
    asm("{ .reg .u64 t; cvta.to.shared.u64 t, %1; cvt.u32.u64 %0, t; }" : "=r"(a) : "l"(p));
    return a;
}
__device__ __forceinline__ void cp_async16(uint32_t dst, const void* src, int sz) {
    asm volatile("cp.async.cg.shared.global [%0], [%1], 16, %2;"
                 :: "r"(dst), "l"(src), "r"(sz) : "memory");
}
#define CP_COMMIT() asm volatile("cp.async.commit_group;" ::: "memory")
#define CP_WAIT3()  asm volatile("cp.async.wait_group 3;" ::: "memory")

__device__ __forceinline__ void ldm_x4(uint32_t* d, uint32_t addr) {
    asm volatile("ldmatrix.sync.aligned.m8n8.x4.shared.b16 {%0,%1,%2,%3}, [%4];"
                 : "=r"(d[0]), "=r"(d[1]), "=r"(d[2]), "=r"(d[3]) : "r"(addr));
}
__device__ __forceinline__ void mma_f16(float* c, const uint32_t* a, const uint32_t* b) {
    asm volatile("mma.sync.aligned.m16n8k16.row.col.f32.f16.f16.f32 "
                 "{%0,%1,%2,%3}, {%4,%5,%6,%7}, {%8,%9}, {%0,%1,%2,%3};"
                 : "+f"(c[0]), "+f"(c[1]), "+f"(c[2]), "+f"(c[3])
                 : "r"(a[0]), "r"(a[1]), "r"(a[2]), "r"(a[3]), "r"(b[0]), "r"(b[1]));
}

// ---------------- 0. zero small state ----------------
__global__ void zero_small_kernel() {
    int i = blockIdx.x * blockDim.x + threadIdx.x;
    if (i < N_NODES) { g_deg[i] = 0; g_cursor[i] = 0; }
}

// ---------------- 1. histogram in-degree ----------------
__global__ void hist_kernel(const int* __restrict__ dst) {
    int e = blockIdx.x * blockDim.x + threadIdx.x;
    if (e < N_EDGES) atomicAdd(&g_deg[dst[e]], 1);
}

// ---------------- 2. exclusive scan of g_deg -> g_off (3 kernels) ----------
__global__ void scan1_kernel() {
    __shared__ int s[256];
    int t = threadIdx.x;
    int i = blockIdx.x * 256 + t;
    int v = (i < N_NODES) ? g_deg[i] : 0;
    s[t] = v;
    __syncthreads();
#pragma unroll
    for (int o = 1; o < 256; o <<= 1) {
        int tv = (t >= o) ? s[t - o] : 0;
        __syncthreads();
        s[t] += tv;
        __syncthreads();
    }
    if (i < N_NODES) g_off[i] = s[t] - v;
    if (t == 255) g_bsum[blockIdx.x] = s[255];
}
__global__ void scan2_kernel() {
    __shared__ int s[256];
    int t = threadIdx.x;
    int v = (t < NSCAN_BLKS) ? g_bsum[t] : 0;
    s[t] = v;
    __syncthreads();
#pragma unroll
    for (int o = 1; o < 256; o <<= 1) {
        int tv = (t >= o) ? s[t - o] : 0;
        __syncthreads();
        s[t] += tv;
        __syncthreads();
    }
    if (t < NSCAN_BLKS) g_bsum[t] = s[t] - v;
}
__global__ void scan3_kernel() {
    int t = threadIdx.x;
    int i = blockIdx.x * 256 + t;
    if (i < N_NODES) g_off[i] += g_bsum[blockIdx.x];
}

// ---------------- 3. fill CSR ----------------
__global__ void fill_kernel(const int* __restrict__ src, const int* __restrict__ dst) {
    int e = blockIdx.x * blockDim.x + threadIdx.x;
    if (e >= N_EDGES) return;
    int d = dst[e];
    int p = g_off[d] + atomicAdd(&g_cursor[d], 1);
    g_csr[p] = src[e];
}

// ---------------- 4. aggregate + convert: g_A[row] = fp16([x | -mean]) -----
__global__ __launch_bounds__(128)
void agg_kernel(const float* __restrict__ x) {
    int node = blockIdx.x;
    int t = threadIdx.x;               // 0..127, owns 4 floats
    int off = g_off[node];
    int deg = g_deg[node];

    float4 acc = make_float4(0.f, 0.f, 0.f, 0.f);
    for (int e = 0; e < deg; e++) {
        int s = g_csr[off + e];
        float4 v = *reinterpret_cast<const float4*>(x + (size_t)s * D + t * 4);
        acc.x += v.x; acc.y += v.y; acc.z += v.z; acc.w += v.w;
    }
    float sc = (deg > 0) ? (-1.0f / (float)deg) : 0.f;
    acc.x *= sc; acc.y *= sc; acc.z *= sc; acc.w *= sc;

    float4 xv = *reinterpret_cast<const float4*>(x + (size_t)node * D + t * 4);

    __half2 xh0 = __floats2half2_rn(xv.x, xv.y);
    __half2 xh1 = __floats2half2_rn(xv.z, xv.w);
    __half2 mh0 = __floats2half2_rn(acc.x, acc.y);
    __half2 mh1 = __floats2half2_rn(acc.z, acc.w);

    uint2 xw = make_uint2(*reinterpret_cast<uint32_t*>(&xh0), *reinterpret_cast<uint32_t*>(&xh1));
    uint2 mw = make_uint2(*reinterpret_cast<uint32_t*>(&mh0), *reinterpret_cast<uint32_t*>(&mh1));
    *reinterpret_cast<uint2*>(g_A + (size_t)node * KTOT + t * 4)     = xw;
    *reinterpret_cast<uint2*>(g_A + (size_t)node * KTOT + D + t * 4) = mw;
}

// ---------------- 5a. bc = b1 + b2 ----------------
__global__ void bias_kernel(const float* __restrict__ b1, const float* __restrict__ b2) {
    int i = blockIdx.x * blockDim.x + threadIdx.x;
    if (i < D) g_bc[i] = b1[i] + b2[i];
}

// ---------------- 5b. BtHi/BtLo = fp16 hi/lo of transpose([[W1+W2],[W2]]) --
__global__ void bprep_kernel(const float* __restrict__ W1, const float* __restrict__ W2) {
    __shared__ float tile[32][33];
    int k0 = blockIdx.x * 32, n0 = blockIdx.y * 32;
    int kk = k0 + threadIdx.y, nn = n0 + threadIdx.x;
    float v = (kk < D) ? (W1[kk * D + nn] + W2[kk * D + nn]) : W2[(kk - D) * D + nn];
    tile[threadIdx.y][threadIdx.x] = v;
    __syncthreads();
    int wn = n0 + threadIdx.y, wk = k0 + threadIdx.x;
    float v2 = tile[threadIdx.x][threadIdx.y];
    __half h = __float2half_rn(v2);
    __half l = __float2half_rn(v2 - __half2float(h));
    g_BtHi[(size_t)wn * KTOT + wk] = h;
    g_BtLo[(size_t)wn * KTOT + wk] = l;
}

// ---------------- 6. fp16 mma.sync GEMM, 2 terms (A@Bhi + A@Blo) -----------
#define BM 128
#define BN 128
#define BKE 32                      // fp16 K elems per chunk
#define ROWB 80                     // 64B data + 16B pad per row
#define TILE_B (128 * ROWB)         // 10240 B
#define STAGE_B (3 * TILE_B)        // A, Bhi, Blo
#define NSTAGE 4
#define NCHUNK (KTOT / BKE)         // 32
#define GEMM_SMEM (NSTAGE * STAGE_B)

__device__ __forceinline__ void load_stage(uint32_t sbase, int tid,
                                           int block_row, int block_col, int kt) {
#pragma unroll
    for (int l = 0; l < 6; l++) {
        int idx  = tid + l * 256;        // 0..1535
        int tile = idx >> 9;             // 0:A 1:Bhi 2:Blo
        int rem  = idx & 511;
        int r    = rem >> 2;             // row 0..127
        int g    = rem & 3;              // 16B granule
        uint32_t dstp = sbase + tile * TILE_B + r * ROWB + g * 16;
        const __half* src;
        int sz = 16;
        if (tile == 0) {
            int grow = block_row + r;
            if (grow >= N_NODES) { grow = N_NODES - 1; sz = 0; }
            src = g_A + (size_t)grow * KTOT + kt + g * 8;
        } else {
            src = (tile == 1 ? g_BtHi : g_BtLo) + (size_t)(block_col + r) * KTOT + kt + g * 8;
        }
        cp_async16(dstp, src, sz);
    }
}

__global__ __launch_bounds__(256, 1)
void gemm_mma_kernel(const float* __restrict__ x, float* __restrict__ out) {
    extern __shared__ char smem[];
    const uint32_t sb0 = smem_u32(smem);
    const int tid  = threadIdx.x;
    const int wid  = tid >> 5;
    const int lane = tid & 31;
    const int block_row = blockIdx.y * BM;
    const int block_col = blockIdx.x * BN;
    const int m0w = (wid & 3) * 32;
    const int n0w = (wid >> 2) * 64;

    float acc[2][8][4];
#pragma unroll
    for (int i = 0; i < 2; i++)
#pragma unroll
        for (int j = 0; j < 8; j++)
#pragma unroll
            for (int q = 0; q < 4; q++) acc[i][j][q] = 0.f;

#pragma unroll
    for (int s = 0; s < NSTAGE; s++) {
        load_stage(sb0 + s * STAGE_B, tid, block_row, block_col, s * BKE);
        CP_COMMIT();
    }

    const int arow    = lane & 15;
    const int acoloff = (lane >> 4) * 8;
    const int bq      = lane >> 3;
    const int brow    = ((bq >> 1) * 8) + (lane & 7);
    const int bkoff   = (bq & 1) * 8;

    for (int c = 0; c < NCHUNK; c++) {
        CP_WAIT3();
        __syncthreads();
        const uint32_t sb = sb0 + (c % NSTAGE) * STAGE_B;

#pragma unroll
        for (int ks = 0; ks < 2; ks++) {
            uint32_t a[2][4], bhi[8][2], blo[8][2];
#pragma unroll
            for (int i = 0; i < 2; i++) {
                uint32_t ad = sb + (m0w + i * 16 + arow) * ROWB + (ks * 16 + acoloff) * 2;
                ldm_x4(a[i], ad);
            }
#pragma unroll
            for (int jj = 0; jj < 4; jj++) {
                uint32_t bd = sb + TILE_B + (n0w + jj * 16 + brow) * ROWB + (ks * 16 + bkoff) * 2;
                uint32_t r4[4];
                ldm_x4(r4, bd);
                bhi[jj*2][0] = r4[0]; bhi[jj*2][1] = r4[1];
                bhi[jj*2+1][0] = r4[2]; bhi[jj*2+1][1] = r4[3];
                ldm_x4(r4, bd + TILE_B);
                blo[jj*2][0] = r4[0]; blo[jj*2][1] = r4[1];
                blo[jj*2+1][0] = r4[2]; blo[jj*2+1][1] = r4[3];
            }
#pragma unroll
            for (int i = 0; i < 2; i++)
#pragma unroll
                for (int j = 0; j < 8; j++) {
                    mma_f16(acc[i][j], a[i], bhi[j]);
                    mma_f16(acc[i][j], a[i], blo[j]);
                }
        }
        __syncthreads();
        if (c + NSTAGE < NCHUNK)
            load_stage(sb, tid, block_row, block_col, (c + NSTAGE) * BKE);
        CP_COMMIT();
    }

    // epilogue: bias + degree-0 passthrough
#pragma unroll
    for (int i = 0; i < 2; i++) {
        int r0 = block_row + m0w + i * 16 + (lane >> 2);
        int r1 = r0 + 8;
        bool v0 = r0 < N_NODES, v1 = r1 < N_NODES;
        int c0 = v0 ? g_deg[r0] : 0;
        int c1 = v1 ? g_deg[r1] : 0;
#pragma unroll
        for (int j = 0; j < 8; j++) {
            int col = block_col + n0w + j * 8 + (lane & 3) * 2;
            float b0 = g_bc[col], b1 = g_bc[col + 1];
            if (v0) {
                float2 o;
                if (c0 > 0) { o.x = acc[i][j][0] + b0; o.y = acc[i][j][1] + b1; }
                else { o = *reinterpret_cast<const float2*>(x + (size_t)r0 * D + col); }
                *reinterpret_cast<float2*>(out + (size_t)r0 * D + col) = o;
            }
            if (v1) {
                float2 o;
                if (c1 > 0) { o.x = acc[i][j][2] + b0; o.y = acc[i][j][3] + b1; }
                else { o = *reinterpret_cast<const float2*>(x + (size_t)r1 * D + col); }
                *reinterpret_cast<float2*>(out + (size_t)r1 * D + col) = o;
            }
        }
    }
}

// ---------------- launch ----------------
extern "C" void kernel_launch(void* const* d_in, const int* in_sizes, int n_in,
                              void* d_out, int out_size) {
    const float* x   = (const float*)d_in[0];
    const int*   src = (const int*)d_in[1];
    const int*   dst = (const int*)d_in[2];
    const float* W1  = (const float*)d_in[3];
    const float* b1  = (const float*)d_in[4];
    const float* W2  = (const float*)d_in[5];
    const float* b2  = (const float*)d_in[6];
    float* out = (float*)d_out;

    cudaFuncSetAttribute(gemm_mma_kernel, cudaFuncAttributeMaxDynamicSharedMemorySize, GEMM_SMEM);

    zero_small_kernel<<<NSCAN_BLKS, 256>>>();
    hist_kernel<<<(N_EDGES + 255) / 256, 256>>>(dst);
    scan1_kernel<<<NSCAN_BLKS, 256>>>();
    scan2_kernel<<<1, 256>>>();
    scan3_kernel<<<NSCAN_BLKS, 256>>>();
    fill_kernel<<<(N_EDGES + 255) / 256, 256>>>(src, dst);
    bias_kernel<<<2, 256>>>(b1, b2);
    {
        dim3 bg(KTOT / 32, D / 32);
        dim3 bb(32, 32);
        bprep_kernel<<<bg, bb>>>(W1, W2);
    }
    agg_kernel<<<N_NODES, 128>>>(x);
    {
        dim3 grid(D / BN, (N_NODES + BM - 1) / BM);
        gemm_mma_kernel<<<grid, 256, GEMM_SMEM>>>(x, out);
    }
}

// round 5
// speedup vs baseline: 5.3237x; 1.7655x over previous
#include <cuda_runtime.h>
#include <cuda_fp16.h>
#include <cstdint>

#define N_NODES 50000
#define D 512
#define N_EDGES 400000
#define KTOT 1024
#define NSCAN_BLKS 196   // ceil(50000/256)

// ---------------- scratch (device globals: allocation-free) ----------------
__device__ __align__(16) int   g_deg[N_NODES];
__device__ __align__(16) int   g_off[N_NODES];
__device__ __align__(16) int   g_cursor[N_NODES];
__device__ __align__(16) int   g_bsum[256];
__device__ __align__(16) int   g_csr[N_EDGES];                    // src per CSR slot
__device__ __align__(16) float g_bc[D];                           // b1 + b2
__device__ __align__(16) __half g_A[(size_t)N_NODES * KTOT];      // [x | -mean] fp16
__device__ __align__(16) __half g_Bt[(size_t)D * KTOT];           // Bt[n][k] fp16

// ---------------- asm helpers ----------------
__device__ __forceinline__ uint32_t smem_u32(const void* p) {
    uint32_t a;
    asm("{ .reg .u64 t; cvta.to.shared.u64 t, %1; cvt.u32.u64 %0, t; }" : "=r"(a) : "l"(p));
    return a;
}
__device__ __forceinline__ void cp_async16(uint32_t dst, const void* src, int sz) {
    asm volatile("cp.async.cg.shared.global [%0], [%1], 16, %2;"
                 :: "r"(dst), "l"(src), "r"(sz) : "memory");
}
#define CP_COMMIT() asm volatile("cp.async.commit_group;" ::: "memory")
#define CP_WAIT3()  asm volatile("cp.async.wait_group 3;" ::: "memory")

__device__ __forceinline__ void ldm_x4(uint32_t* d, uint32_t addr) {
    asm volatile("ldmatrix.sync.aligned.m8n8.x4.shared.b16 {%0,%1,%2,%3}, [%4];"
                 : "=r"(d[0]), "=r"(d[1]), "=r"(d[2]), "=r"(d[3]) : "r"(addr));
}
__device__ __forceinline__ void mma_f16(float* c, const uint32_t* a, const uint32_t* b) {
    asm volatile("mma.sync.aligned.m16n8k16.row.col.f32.f16.f16.f32 "
                 "{%0,%1,%2,%3}, {%4,%5,%6,%7}, {%8,%9}, {%0,%1,%2,%3};"
                 : "+f"(c[0]), "+f"(c[1]), "+f"(c[2]), "+f"(c[3])
                 : "r"(a[0]), "r"(a[1]), "r"(a[2]), "r"(a[3]), "r"(b[0]), "r"(b[1]));
}

// ---------------- 0. zero small state ----------------
__global__ void zero_small_kernel() {
    int i = blockIdx.x * blockDim.x + threadIdx.x;
    if (i < N_NODES) { g_deg[i] = 0; g_cursor[i] = 0; }
}

// ---------------- 1. histogram in-degree ----------------
__global__ void hist_kernel(const int* __restrict__ dst) {
    int e = blockIdx.x * blockDim.x + threadIdx.x;
    if (e < N_EDGES) atomicAdd(&g_deg[dst[e]], 1);
}

// ---------------- 2. exclusive scan of g_deg -> g_off ----------------------
__global__ void scan1_kernel() {
    __shared__ int s[256];
    int t = threadIdx.x;
    int i = blockIdx.x * 256 + t;
    int v = (i < N_NODES) ? g_deg[i] : 0;
    s[t] = v;
    __syncthreads();
#pragma unroll
    for (int o = 1; o < 256; o <<= 1) {
        int tv = (t >= o) ? s[t - o] : 0;
        __syncthreads();
        s[t] += tv;
        __syncthreads();
    }
    if (i < N_NODES) g_off[i] = s[t] - v;
    if (t == 255) g_bsum[blockIdx.x] = s[255];
}
__global__ void scan2_kernel() {
    __shared__ int s[256];
    int t = threadIdx.x;
    int v = (t < NSCAN_BLKS) ? g_bsum[t] : 0;
    s[t] = v;
    __syncthreads();
#pragma unroll
    for (int o = 1; o < 256; o <<= 1) {
        int tv = (t >= o) ? s[t - o] : 0;
        __syncthreads();
        s[t] += tv;
        __syncthreads();
    }
    if (t < NSCAN_BLKS) g_bsum[t] = s[t] - v;
}
__global__ void scan3_kernel() {
    int t = threadIdx.x;
    int i = blockIdx.x * 256 + t;
    if (i < N_NODES) g_off[i] += g_bsum[blockIdx.x];
}

// ---------------- 3. fill CSR ----------------
__global__ void fill_kernel(const int* __restrict__ src, const int* __restrict__ dst) {
    int e = blockIdx.x * blockDim.x + threadIdx.x;
    if (e >= N_EDGES) return;
    int d = dst[e];
    int p = g_off[d] + atomicAdd(&g_cursor[d], 1);
    g_csr[p] = src[e];
}

// ---------------- 4a. xconv: g_A[:,0:512] = fp16(x) ------------------------
__global__ void xconv_kernel(const float* __restrict__ x) {
    int idx = blockIdx.x * blockDim.x + threadIdx.x;   // over 50000*128 vec4 groups
    if (idx >= N_NODES * (D / 4)) return;
    int row = idx >> 7;
    int c4  = (idx & 127) * 4;
    float4 v = *reinterpret_cast<const float4*>(x + (size_t)row * D + c4);
    __half2 h0 = __floats2half2_rn(v.x, v.y);
    __half2 h1 = __floats2half2_rn(v.z, v.w);
    uint2 w = make_uint2(*reinterpret_cast<uint32_t*>(&h0), *reinterpret_cast<uint32_t*>(&h1));
    *reinterpret_cast<uint2*>(g_A + (size_t)row * KTOT + c4) = w;
}

// ---------------- 4b. aggregate: g_A[:,512:1024] = fp16(-mean) -------------
// gathers fp16 rows from g_A (51MB image -> L2-resident)
__global__ __launch_bounds__(128)
void agg_kernel() {
    int node = blockIdx.x;
    int t = threadIdx.x;               // 0..127, owns 4 halves
    int off = g_off[node];
    int deg = g_deg[node];

    float ax = 0.f, ay = 0.f, az = 0.f, aw = 0.f;
    for (int e = 0; e < deg; e++) {
        int s = g_csr[off + e];
        uint2 w = *reinterpret_cast<const uint2*>(g_A + (size_t)s * KTOT + t * 4);
        float2 f0 = __half22float2(*reinterpret_cast<__half2*>(&w.x));
        float2 f1 = __half22float2(*reinterpret_cast<__half2*>(&w.y));
        ax += f0.x; ay += f0.y; az += f1.x; aw += f1.y;
    }
    float sc = (deg > 0) ? (-1.0f / (float)deg) : 0.f;
    __half2 m0 = __floats2half2_rn(ax * sc, ay * sc);
    __half2 m1 = __floats2half2_rn(az * sc, aw * sc);
    uint2 w = make_uint2(*reinterpret_cast<uint32_t*>(&m0), *reinterpret_cast<uint32_t*>(&m1));
    *reinterpret_cast<uint2*>(g_A + (size_t)node * KTOT + D + t * 4) = w;
}

// ---------------- 5a. bc = b1 + b2 ----------------
__global__ void bias_kernel(const float* __restrict__ b1, const float* __restrict__ b2) {
    int i = blockIdx.x * blockDim.x + threadIdx.x;
    if (i < D) g_bc[i] = b1[i] + b2[i];
}

// ---------------- 5b. g_Bt = fp16 of transpose([[W1+W2],[W2]]) -------------
__global__ void bprep_kernel(const float* __restrict__ W1, const float* __restrict__ W2) {
    __shared__ float tile[32][33];
    int k0 = blockIdx.x * 32, n0 = blockIdx.y * 32;
    int kk = k0 + threadIdx.y, nn = n0 + threadIdx.x;
    float v = (kk < D) ? (W1[kk * D + nn] + W2[kk * D + nn]) : W2[(kk - D) * D + nn];
    tile[threadIdx.y][threadIdx.x] = v;
    __syncthreads();
    int wn = n0 + threadIdx.y, wk = k0 + threadIdx.x;
    g_Bt[(size_t)wn * KTOT + wk] = __float2half_rn(tile[threadIdx.x][threadIdx.y]);
}

// ---------------- 6. fp16 mma.sync GEMM, single term -----------------------
#define BM 128
#define BN 128
#define BKE 32                      // fp16 K elems per chunk
#define ROWB 80                     // 64B data + 16B pad per row
#define TILE_B (128 * ROWB)         // 10240 B
#define STAGE_B (2 * TILE_B)        // A, B
#define NSTAGE 4
#define NCHUNK (KTOT / BKE)         // 32
#define GEMM_SMEM (NSTAGE * STAGE_B)

__device__ __forceinline__ void load_stage(uint32_t sbase, int tid,
                                           int block_row, int block_col, int kt) {
#pragma unroll
    for (int l = 0; l < 4; l++) {
        int idx  = tid + l * 256;        // 0..1023
        int tile = idx >> 9;             // 0:A 1:B
        int rem  = idx & 511;
        int r    = rem >> 2;             // row 0..127
        int g    = rem & 3;              // 16B granule
        uint32_t dstp = sbase + tile * TILE_B + r * ROWB + g * 16;
        const __half* src;
        int sz = 16;
        if (tile == 0) {
            int grow = block_row + r;
            if (grow >= N_NODES) { grow = N_NODES - 1; sz = 0; }
            src = g_A + (size_t)grow * KTOT + kt + g * 8;
        } else {
            src = g_Bt + (size_t)(block_col + r) * KTOT + kt + g * 8;
        }
        cp_async16(dstp, src, sz);
    }
}

__global__ __launch_bounds__(256, 2)
void gemm_mma_kernel(const float* __restrict__ x, float* __restrict__ out) {
    extern __shared__ char smem[];
    const uint32_t sb0 = smem_u32(smem);
    const int tid  = threadIdx.x;
    const int wid  = tid >> 5;
    const int lane = tid & 31;
    const int block_row = blockIdx.y * BM;
    const int block_col = blockIdx.x * BN;
    const int m0w = (wid & 3) * 32;
    const int n0w = (wid >> 2) * 64;

    float acc[2][8][4];
#pragma unroll
    for (int i = 0; i < 2; i++)
#pragma unroll
        for (int j = 0; j < 8; j++)
#pragma unroll
            for (int q = 0; q < 4; q++) acc[i][j][q] = 0.f;

#pragma unroll
    for (int s = 0; s < NSTAGE; s++) {
        load_stage(sb0 + s * STAGE_B, tid, block_row, block_col, s * BKE);
        CP_COMMIT();
    }

    const int arow    = lane & 15;
    const int acoloff = (lane >> 4) * 8;
    const int bq      = lane >> 3;
    const int brow    = ((bq >> 1) * 8) + (lane & 7);
    const int bkoff   = (bq & 1) * 8;

    for (int c = 0; c < NCHUNK; c++) {
        CP_WAIT3();
        __syncthreads();
        const uint32_t sb = sb0 + (c % NSTAGE) * STAGE_B;

#pragma unroll
        for (int ks = 0; ks < 2; ks++) {
            uint32_t a[2][4], b[8][2];
#pragma unroll
            for (int i = 0; i < 2; i++) {
                uint32_t ad = sb + (m0w + i * 16 + arow) * ROWB + (ks * 16 + acoloff) * 2;
                ldm_x4(a[i], ad);
            }
#pragma unroll
            for (int jj = 0; jj < 4; jj++) {
                uint32_t bd = sb + TILE_B + (n0w + jj * 16 + brow) * ROWB + (ks * 16 + bkoff) * 2;
                uint32_t r4[4];
                ldm_x4(r4, bd);
                b[jj*2][0] = r4[0]; b[jj*2][1] = r4[1];
                b[jj*2+1][0] = r4[2]; b[jj*2+1][1] = r4[3];
            }
#pragma unroll
            for (int i = 0; i < 2; i++)
#pragma unroll
                for (int j = 0; j < 8; j++)
                    mma_f16(acc[i][j], a[i], b[j]);
        }
        __syncthreads();
        if (c + NSTAGE < NCHUNK)
            load_stage(sb, tid, block_row, block_col, (c + NSTAGE) * BKE);
        CP_COMMIT();
    }

    // epilogue: bias + degree-0 passthrough
#pragma unroll
    for (int i = 0; i < 2; i++) {
        int r0 = block_row + m0w + i * 16 + (lane >> 2);
        int r1 = r0 + 8;
        bool v0 = r0 < N_NODES, v1 = r1 < N_NODES;
        int c0 = v0 ? g_deg[r0] : 0;
        int c1 = v1 ? g_deg[r1] : 0;
#pragma unroll
        for (int j = 0; j < 8; j++) {
            int col = block_col + n0w + j * 8 + (lane & 3) * 2;
            float b0 = g_bc[col], b1 = g_bc[col + 1];
            if (v0) {
                float2 o;
                if (c0 > 0) { o.x = acc[i][j][0] + b0; o.y = acc[i][j][1] + b1; }
                else { o = *reinterpret_cast<const float2*>(x + (size_t)r0 * D + col); }
                *reinterpret_cast<float2*>(out + (size_t)r0 * D + col) = o;
            }
            if (v1) {
                float2 o;
                if (c1 > 0) { o.x = acc[i][j][2] + b0; o.y = acc[i][j][3] + b1; }
                else { o = *reinterpret_cast<const float2*>(x + (size_t)r1 * D + col); }
                *reinterpret_cast<float2*>(out + (size_t)r1 * D + col) = o;
            }
        }
    }
}

// ---------------- launch ----------------
extern "C" void kernel_launch(void* const* d_in, const int* in_sizes, int n_in,
                              void* d_out, int out_size) {
    const float* x   = (const float*)d_in[0];
    const int*   src = (const int*)d_in[1];
    const int*   dst = (const int*)d_in[2];
    const float* W1  = (const float*)d_in[3];
    const float* b1  = (const float*)d_in[4];
    const float* W2  = (const float*)d_in[5];
    const float* b2  = (const float*)d_in[6];
    float* out = (float*)d_out;

    cudaFuncSetAttribute(gemm_mma_kernel, cudaFuncAttributeMaxDynamicSharedMemorySize, GEMM_SMEM);

    zero_small_kernel<<<NSCAN_BLKS, 256>>>();
    hist_kernel<<<(N_EDGES + 255) / 256, 256>>>(dst);
    scan1_kernel<<<NSCAN_BLKS, 256>>>();
    scan2_kernel<<<1, 256>>>();
    scan3_kernel<<<NSCAN_BLKS, 256>>>();
    fill_kernel<<<(N_EDGES + 255) / 256, 256>>>(src, dst);
    xconv_kernel<<<(N_NODES * (D / 4) + 255) / 256, 256>>>(x);
    bias_kernel<<<2, 256>>>(b1, b2);
    {
        dim3 bg(KTOT / 32, D / 32);
        dim3 bb(32, 32);
        bprep_kernel<<<bg, bb>>>(W1, W2);
    }
    agg_kernel<<<N_NODES, 128>>>();
    {
        dim3 grid(D / BN, (N_NODES + BM - 1) / BM);
        gemm_mma_kernel<<<grid, 256, GEMM_SMEM>>>(x, out);
    }
}